// round 7
// baseline (speedup 1.0000x reference)
#include <cuda_runtime.h>
#include <math.h>

// ---------------------------------------------------------------------------
// RolloutModule: 64-step closed-loop MLP policy rollout + STREL robustness.
// One CTA = 64 agents, runs all 64 steps privately (agents independent).
// fp32 baseline: register-blocked 8x8 GEMM tiles, activations in smem
// neuron-major [k][m], weights W2/W3 streamed from L2 in 16-row tiles with
// register prefetch. Online (streaming) stable logsumexp for the temporal
// reductions so no trajectory is stored.
// ---------------------------------------------------------------------------

#define NT   256     // threads per CTA
#define AG   64      // agents per CTA
#define HD   256     // hidden size
#define TK   16      // k-tile rows for streamed W2/W3
#define NSTEP 64

struct __align__(16) Smem {
    float Hbuf[HD * AG];     // activations, [n][m] neuron-major  (64 KB)
    float Obs[16 * AG];      // observation,  [k][m], 13 rows used (4 KB)
    float Wt[TK * HD];       // streamed weight tile [k][n]       (16 KB)
    float W1s[13 * HD];      // resident layer-1 weights          (13 KB)
    float b1s[HD];
    float b2s[HD];
    float b3s[HD];
    float wmuT[2 * HD];      // output weights transposed [d][k]
    float bmus[4];
    float act[2 * AG];       // actions [d][m]
};

__device__ __forceinline__ float clampf(float v, float lo, float hi) {
    return fminf(fmaxf(v, lo), hi);
}

__global__ __launch_bounds__(NT, 2)
void rollout_kernel(const float* __restrict__ pos0,
                    const float* __restrict__ wind,
                    const float* __restrict__ w1, const float* __restrict__ b1,
                    const float* __restrict__ w2, const float* __restrict__ b2,
                    const float* __restrict__ w3, const float* __restrict__ b3,
                    const float* __restrict__ wmu, const float* __restrict__ bmu,
                    float* __restrict__ out)
{
    extern __shared__ char smraw[];
    Smem& sm = *reinterpret_cast<Smem*>(smraw);

    const int t    = threadIdx.x;
    const int lane = t & 31;
    // GEMM thread tile: 8 agents (m) x 8 neurons (n) per thread.
    const int mb = (lane & 7) << 3;                         // m base: 0..56
    const int nb = ((t >> 5) << 5) + ((lane >> 3) << 3);    // n base: 0..248

    // ---- load resident weights into smem --------------------------------
    for (int i = t; i < 13 * HD; i += NT) sm.W1s[i] = w1[i];
    for (int i = t; i < HD; i += NT) {
        sm.b1s[i] = b1[i]; sm.b2s[i] = b2[i]; sm.b3s[i] = b3[i];
    }
    for (int i = t; i < 2 * HD; i += NT) {
        // wmu global layout (256,2): wmu[k*2+d] -> wmuT[d*256+k]
        sm.wmuT[(i & 1) * HD + (i >> 1)] = wmu[i];
    }
    if (t < 2) sm.bmus[t] = bmu[t];

    // ---- per-agent state (threads 0..63) --------------------------------
    const int gid = blockIdx.x * AG + t;
    float px = 0.f, py = 0.f, wx = 0.f, wy = 0.f;
    float mxs = -INFINITY, ss = 0.f;   // online LSE for -8*safe_margin
    float mxr = -INFINITY, sr = 0.f;   // online LSE for  8*reach_margin
    if (t < AG) {
        px = pos0[gid * 2];  py = pos0[gid * 2 + 1];
        wx = wind[gid * 2];  wy = wind[gid * 2 + 1];
    }
    __syncthreads();

    for (int step = 0; step < NSTEP; ++step) {
        // ---------------- observe (one thread per agent) -----------------
        if (t < AG) {
            sm.Obs[0 * AG + t] = px * 0.1f;
            sm.Obs[1 * AG + t] = py * 0.1f;
            sm.Obs[2 * AG + t] = (4.0f - px) * 0.1f;
            sm.Obs[3 * AG + t] = (3.0f - py) * 0.1f;
            sm.Obs[4 * AG + t] = (1.75f - px) * 0.1f;
            sm.Obs[5 * AG + t] = (1.75f - py) * 0.1f;
            sm.Obs[6 * AG + t] = (1.75f - px) * 0.1f;
            sm.Obs[7 * AG + t] = (3.75f - py) * 0.1f;
            sm.Obs[8 * AG + t] = (3.75f - px) * 0.1f;
            sm.Obs[9 * AG + t] = (2.0f  - py) * 0.1f;
            {
                float dx = px - 1.75f, dy = py - 1.75f;
                sm.Obs[10 * AG + t] = sqrtf(dx*dx + dy*dy + 1e-9f) - 0.38f;
            }
            {
                float dx = px - 1.75f, dy = py - 3.75f;
                sm.Obs[11 * AG + t] = sqrtf(dx*dx + dy*dy + 1e-9f) - 0.42f;
            }
            {
                float dx = px - 3.75f, dy = py - 2.0f;
                sm.Obs[12 * AG + t] = sqrtf(dx*dx + dy*dy + 1e-9f) - 0.34f;
            }
        }
        __syncthreads();

        float acc[8][8];

        // ---------------- layer 1: 13 -> 256 -----------------------------
        #pragma unroll
        for (int i = 0; i < 8; ++i)
            #pragma unroll
            for (int j = 0; j < 8; ++j) acc[i][j] = 0.f;

        #pragma unroll
        for (int k = 0; k < 13; ++k) {
            const float* Hr = &sm.Obs[k * AG + mb];
            float4 av0 = *(const float4*)Hr;
            float4 av1 = *(const float4*)(Hr + 4);
            float av[8] = {av0.x, av0.y, av0.z, av0.w, av1.x, av1.y, av1.z, av1.w};
            const float* Br = &sm.W1s[k * HD + nb];
            float4 bv0 = *(const float4*)Br;
            float4 bv1 = *(const float4*)(Br + 4);
            float bv[8] = {bv0.x, bv0.y, bv0.z, bv0.w, bv1.x, bv1.y, bv1.z, bv1.w};
            #pragma unroll
            for (int i = 0; i < 8; ++i)
                #pragma unroll
                for (int j = 0; j < 8; ++j)
                    acc[i][j] = fmaf(av[j], bv[i], acc[i][j]);
        }
        // bias + relu, store [n][m]
        #pragma unroll
        for (int i = 0; i < 8; ++i) {
            float bi = sm.b1s[nb + i];
            #pragma unroll
            for (int j = 0; j < 8; ++j)
                sm.Hbuf[(nb + i) * AG + mb + j] = fmaxf(acc[i][j] + bi, 0.f);
        }
        __syncthreads();

        // ---------------- layers 2 & 3: 256 -> 256 (in-place) ------------
        for (int l = 0; l < 2; ++l) {
            const float4* Wg4  = (const float4*)(l ? w3 : w2);
            const float*  bias = l ? sm.b3s : sm.b2s;

            #pragma unroll
            for (int i = 0; i < 8; ++i)
                #pragma unroll
                for (int j = 0; j < 8; ++j) acc[i][j] = 0.f;

            // register prefetch of first tile
            float4 pf0 = Wg4[t], pf1 = Wg4[t + 256], pf2 = Wg4[t + 512], pf3 = Wg4[t + 768];

            for (int kt = 0; kt < HD; kt += TK) {
                __syncthreads();                 // prior tile fully consumed
                float4* Wt4 = (float4*)sm.Wt;
                Wt4[t] = pf0; Wt4[t + 256] = pf1; Wt4[t + 512] = pf2; Wt4[t + 768] = pf3;
                __syncthreads();
                if (kt + TK < HD) {
                    int base = (kt + TK) * (HD / 4);
                    pf0 = Wg4[base + t];       pf1 = Wg4[base + t + 256];
                    pf2 = Wg4[base + t + 512]; pf3 = Wg4[base + t + 768];
                }
                #pragma unroll
                for (int kk = 0; kk < TK; ++kk) {
                    const float* Hr = &sm.Hbuf[(kt + kk) * AG + mb];
                    float4 av0 = *(const float4*)Hr;
                    float4 av1 = *(const float4*)(Hr + 4);
                    float av[8] = {av0.x, av0.y, av0.z, av0.w, av1.x, av1.y, av1.z, av1.w};
                    const float* Br = &sm.Wt[kk * HD + nb];
                    float4 bv0 = *(const float4*)Br;
                    float4 bv1 = *(const float4*)(Br + 4);
                    float bv[8] = {bv0.x, bv0.y, bv0.z, bv0.w, bv1.x, bv1.y, bv1.z, bv1.w};
                    #pragma unroll
                    for (int i = 0; i < 8; ++i)
                        #pragma unroll
                        for (int j = 0; j < 8; ++j)
                            acc[i][j] = fmaf(av[j], bv[i], acc[i][j]);
                }
            }
            __syncthreads();                     // all reads of Hbuf done
            #pragma unroll
            for (int i = 0; i < 8; ++i) {
                float bi = bias[nb + i];
                #pragma unroll
                for (int j = 0; j < 8; ++j)
                    sm.Hbuf[(nb + i) * AG + mb + j] = fmaxf(acc[i][j] + bi, 0.f);
            }
            __syncthreads();
        }

        // ---------------- output layer: 256 -> 2, clip -------------------
        if (t < 2 * AG) {
            const int d = t >> 6, m = t & 63;
            float s = sm.bmus[d];
            const float* wr = &sm.wmuT[d * HD];
            #pragma unroll 8
            for (int k = 0; k < HD; ++k)
                s = fmaf(wr[k], sm.Hbuf[k * AG + m], s);
            sm.act[d * AG + m] = clampf(s, -1.f, 1.f);
        }
        __syncthreads();

        // ---------------- integrate + margins (one thread per agent) -----
        if (t < AG) {
            float ax = sm.act[t], ay = sm.act[AG + t];
            float vx = 2.f * ax + wx, vy = 2.f * ay + wy;
            #pragma unroll
            for (int s_ = 0; s_ < 4; ++s_) {
                px = clampf(px + 0.0625f * vx, -4.f, 10.f);
                py = clampf(py + 0.0625f * vy, -4.f, 10.f);
            }
            // clearances at post-step position
            float d0x = px - 1.75f, d0y = py - 1.75f;
            float c0 = sqrtf(d0x*d0x + d0y*d0y + 1e-9f) - 0.38f;
            float d1x = px - 1.75f, d1y = py - 3.75f;
            float c1 = sqrtf(d1x*d1x + d1y*d1y + 1e-9f) - 0.42f;
            float d2x = px - 3.75f, d2y = py - 2.0f;
            float c2 = sqrtf(d2x*d2x + d2y*d2y + 1e-9f) - 0.34f;
            // spatial smooth-min, beta=50, stable
            float x0 = -50.f * c0, x1 = -50.f * c1, x2 = -50.f * c2;
            float mM = fmaxf(x0, fmaxf(x1, x2));
            float safe = -(mM + logf(expf(x0 - mM) + expf(x1 - mM) + expf(x2 - mM))) * 0.02f;
            // temporal Always(safe): online LSE of -8*safe
            float xs = -8.f * safe;
            if (xs > mxs) { ss = ss * expf(mxs - xs) + 1.f; mxs = xs; }
            else          { ss += expf(xs - mxs); }
            // Eventually(reach): online LSE of 8*(tol - goal_dist)
            float gx = px - 4.f, gy = py - 3.f;
            float gdist = sqrtf(gx*gx + gy*gy + 1e-9f);
            float xr = 8.f * (0.45f - gdist);
            if (xr > mxr) { sr = sr * expf(mxr - xr) + 1.f; mxr = xr; }
            else          { sr += expf(xr - mxr); }
        }
        // no trailing sync needed: only t<AG touch Obs before the next sync
    }

    // ---- final STREL And(·,·) -------------------------------------------
    if (t < AG) {
        float rho_safe  = -(mxs + logf(ss)) * 0.125f;
        float rho_reach =  (mxr + logf(sr)) * 0.125f;
        float xa = -8.f * rho_safe, xb = -8.f * rho_reach;
        float mm = fmaxf(xa, xb);
        float rho = -(mm + logf(expf(xa - mm) + expf(xb - mm))) * 0.125f;
        out[gid] = rho;
    }
}

extern "C" void kernel_launch(void* const* d_in, const int* in_sizes, int n_in,
                              void* d_out, int out_size)
{
    (void)in_sizes; (void)n_in; (void)out_size;
    const float* pos0 = (const float*)d_in[0];
    const float* wind = (const float*)d_in[1];
    const float* w1   = (const float*)d_in[2];
    const float* b1   = (const float*)d_in[3];
    const float* w2   = (const float*)d_in[4];
    const float* b2   = (const float*)d_in[5];
    const float* w3   = (const float*)d_in[6];
    const float* b3   = (const float*)d_in[7];
    const float* wmu  = (const float*)d_in[8];
    const float* bmu  = (const float*)d_in[9];
    float* out = (float*)d_out;

    const int smem = (int)sizeof(Smem);
    cudaFuncSetAttribute(rollout_kernel,
                         cudaFuncAttributeMaxDynamicSharedMemorySize, smem);
    rollout_kernel<<<32768 / AG, NT, smem>>>(pos0, wind, w1, b1, w2, b2,
                                             w3, b3, wmu, bmu, out);
}

// round 10
// speedup vs baseline: 2.1307x; 2.1307x over previous
#include <cuda_runtime.h>
#include <cuda_fp16.h>
#include <math.h>

// ===========================================================================
// RolloutModule via legacy tensor cores (mma.sync m16n8k16 fp16, fp32 accum).
// Split precision: x = hi + lo (fp16 each); products hi*hi + lo*hi + hi*lo.
// One CTA = 128 agents, 512 threads (16 warps, 4m x 4n, warp tile 32x64).
// Activations in SMEM fp16 hi/lo planes [128][256], XOR-swizzled.
// Weights pre-split+transposed [N][K] by prep kernel; k32 stages streamed with
// cp.async, flat double-buffer schedule (no bubbles across layers/steps).
// ===========================================================================

#define NT    512
#define AGC   128
#define CTAS  256
#define NSTEP 64

// smem byte offsets
#define SM_A    0          // A hi plane [128][256] fp16 = 65536
#define SM_ALO  65536      // A lo plane
#define SM_W1   131072     // W1 hi 8192 + lo 8192
#define SM_WST  147456     // 2 stage buffers x 32768 (each: hi[256][32], lo[256][32])
#define SM_B1   212992
#define SM_B2   214016
#define SM_B3   215040
#define SM_WMU  216064     // wmu0[256], wmu1[256] f32
#define SM_PART 218112     // [2][128][4] f32
#define SM_BMU  222208
#define SM_TOT  222336

// Prepared weights (filled by prep kernel every launch)
__device__ __align__(16) unsigned char g_w23[2][8][32768]; // [layer][k32 stage]
__device__ __align__(16) unsigned char g_w1[16384];        // [plane][256][16]

// ---------------------------------------------------------------------------
__device__ __forceinline__ unsigned smem_u32(const void* p) {
    unsigned a;
    asm("{ .reg .u64 t; cvta.to.shared.u64 t, %1; cvt.u32.u64 %0, t; }"
        : "=r"(a) : "l"(p));
    return a;
}
__device__ __forceinline__ void cp16(unsigned d, const void* s) {
    asm volatile("cp.async.cg.shared.global [%0], [%1], 16;" :: "r"(d), "l"(s));
}
__device__ __forceinline__ void cpcommit() { asm volatile("cp.async.commit_group;" ::: "memory"); }
template<int N> __device__ __forceinline__ void cpwait() {
    asm volatile("cp.async.wait_group %0;" :: "n"(N) : "memory");
}

#define LDSM4(r0,r1,r2,r3,a) \
    asm volatile("ldmatrix.sync.aligned.m8n8.x4.shared.b16 {%0,%1,%2,%3}, [%4];" \
        : "=r"(r0),"=r"(r1),"=r"(r2),"=r"(r3) : "r"(a))

#define MMA(dd, a, b0, b1) \
    asm volatile("mma.sync.aligned.m16n8k16.row.col.f32.f16.f16.f32 " \
        "{%0,%1,%2,%3},{%4,%5,%6,%7},{%8,%9},{%0,%1,%2,%3};" \
        : "+f"((dd)[0]),"+f"((dd)[1]),"+f"((dd)[2]),"+f"((dd)[3]) \
        : "r"((a)[0]),"r"((a)[1]),"r"((a)[2]),"r"((a)[3]),"r"(b0),"r"(b1))

__device__ __forceinline__ float clampf(float v, float lo, float hi) {
    return fminf(fmaxf(v, lo), hi);
}

// A fragment (m16 x k16) from a swizzled [128][256] fp16 plane.
// tiles: 0=(m0-7,klo) 1=(m8-15,klo) 2=(m0-7,khi) 3=(m8-15,khi) -> a0..a3.
__device__ __forceinline__ void ldA(unsigned abase, int mbase, int k16,
                                    unsigned lane, unsigned* r) {
    int row = mbase + (int)(((lane >> 3) & 1) << 3) + (int)(lane & 7);
    int kc  = k16 * 2 + (int)(lane >> 4);
    unsigned addr = abase + (unsigned)(row * 512) +
                    ((unsigned)(kc ^ (row & 7)) << 4);
    LDSM4(r[0], r[1], r[2], r[3], addr);
}

// B fragments for 2 ntiles (n16 x k16) from [N][K] fp16, row stride rs bytes.
// r[0],r[1] = ntile n0 (klo,khi); r[2],r[3] = ntile n0+8.
__device__ __forceinline__ void ldB(unsigned wbase, int nbase, int kc0, int rs,
                                    unsigned lane, unsigned* r) {
    int nrow = nbase + (int)((lane >> 4) << 3) + (int)(lane & 7);
    int kc   = kc0 + (int)((lane >> 3) & 1);
    unsigned addr = wbase + (unsigned)(nrow * rs) + ((unsigned)kc << 4);
    LDSM4(r[0], r[1], r[2], r[3], addr);
}

// One k16 step: 3-product split MMA into d[2][8][4].
__device__ __forceinline__ void kstep(float (*d)[8][4],
                                      unsigned ahib, unsigned alob, int k16,
                                      unsigned whib, unsigned wlob,
                                      int kc0loc, int rs,
                                      int wm, int wn, unsigned lane)
{
    unsigned ah[2][4], al[2][4];
    ldA(ahib, wm * 32,      k16, lane, ah[0]);
    ldA(ahib, wm * 32 + 16, k16, lane, ah[1]);
    ldA(alob, wm * 32,      k16, lane, al[0]);
    ldA(alob, wm * 32 + 16, k16, lane, al[1]);
    #pragma unroll
    for (int bh = 0; bh < 2; ++bh) {
        unsigned bhif[8], blof[8];
        ldB(whib, wn * 64 + bh * 32,      kc0loc, rs, lane, bhif);
        ldB(whib, wn * 64 + bh * 32 + 16, kc0loc, rs, lane, bhif + 4);
        ldB(wlob, wn * 64 + bh * 32,      kc0loc, rs, lane, blof);
        ldB(wlob, wn * 64 + bh * 32 + 16, kc0loc, rs, lane, blof + 4);
        #pragma unroll
        for (int mt = 0; mt < 2; ++mt)
            #pragma unroll
            for (int q = 0; q < 4; ++q) {
                const int nt = bh * 4 + q;
                MMA(d[mt][nt], ah[mt], bhif[q * 2], bhif[q * 2 + 1]);
                MMA(d[mt][nt], al[mt], bhif[q * 2], bhif[q * 2 + 1]);
                MMA(d[mt][nt], ah[mt], blof[q * 2], blof[q * 2 + 1]);
            }
    }
}

// Epilogue: bias+relu; STORE -> write hi/lo planes; DOT -> output-layer dots.
template<bool STORE, bool DOT>
__device__ __forceinline__ void epi(float (*d)[8][4], const float* bias,
                                    char* smem, const float* wmu0,
                                    const float* wmu1,
                                    int wm, int wn, unsigned lane)
{
    const int qrow = (int)(lane >> 2);
    const int qn   = (int)(lane & 3) * 2;
    float* part = (float*)(smem + SM_PART);
    #pragma unroll
    for (int mt = 0; mt < 2; ++mt) {
        const int r0 = wm * 32 + mt * 16 + qrow;
        const int r1 = r0 + 8;
        float s0a = 0.f, s1a = 0.f, s0b = 0.f, s1b = 0.f;
        #pragma unroll
        for (int nt = 0; nt < 8; ++nt) {
            const int n = wn * 64 + nt * 8 + qn;
            const float bb0 = bias[n], bb1 = bias[n + 1];
            float v0 = fmaxf(d[mt][nt][0] + bb0, 0.f);
            float v1 = fmaxf(d[mt][nt][1] + bb1, 0.f);
            float v2 = fmaxf(d[mt][nt][2] + bb0, 0.f);
            float v3 = fmaxf(d[mt][nt][3] + bb1, 0.f);
            if (DOT) {
                s0a = fmaf(v0, wmu0[n], fmaf(v1, wmu0[n + 1], s0a));
                s1a = fmaf(v0, wmu1[n], fmaf(v1, wmu1[n + 1], s1a));
                s0b = fmaf(v2, wmu0[n], fmaf(v3, wmu0[n + 1], s0b));
                s1b = fmaf(v2, wmu1[n], fmaf(v3, wmu1[n + 1], s1b));
            }
            if (STORE) {
                const int chunk = n >> 3, off = (n & 7) * 2;
                __half h0 = __float2half_rn(v0), h1 = __float2half_rn(v1);
                __half h2 = __float2half_rn(v2), h3 = __float2half_rn(v3);
                __half2 hp0 = __halves2half2(h0, h1);
                __half2 hp1 = __halves2half2(h2, h3);
                __half2 lp0 = __halves2half2(
                    __float2half_rn(v0 - __half2float(h0)),
                    __float2half_rn(v1 - __half2float(h1)));
                __half2 lp1 = __halves2half2(
                    __float2half_rn(v2 - __half2float(h2)),
                    __float2half_rn(v3 - __half2float(h3)));
                const int p0 = r0 * 512 + ((chunk ^ (r0 & 7)) << 4) + off;
                const int p1 = r1 * 512 + ((chunk ^ (r1 & 7)) << 4) + off;
                *(__half2*)(smem + SM_A   + p0) = hp0;
                *(__half2*)(smem + SM_ALO + p0) = lp0;
                *(__half2*)(smem + SM_A   + p1) = hp1;
                *(__half2*)(smem + SM_ALO + p1) = lp1;
            }
        }
        if (DOT) {
            s0a += __shfl_xor_sync(0xffffffffu, s0a, 1);
            s0a += __shfl_xor_sync(0xffffffffu, s0a, 2);
            s1a += __shfl_xor_sync(0xffffffffu, s1a, 1);
            s1a += __shfl_xor_sync(0xffffffffu, s1a, 2);
            s0b += __shfl_xor_sync(0xffffffffu, s0b, 1);
            s0b += __shfl_xor_sync(0xffffffffu, s0b, 2);
            s1b += __shfl_xor_sync(0xffffffffu, s1b, 1);
            s1b += __shfl_xor_sync(0xffffffffu, s1b, 2);
            if ((lane & 3) == 0) {
                part[r0 * 4 + wn]       = s0a;
                part[512 + r0 * 4 + wn] = s1a;
                part[r1 * 4 + wn]       = s0b;
                part[512 + r1 * 4 + wn] = s1b;
            }
        }
    }
}

__device__ __forceinline__ void copy32k(unsigned dst, const unsigned char* src, int t) {
    #pragma unroll
    for (int i = 0; i < 4; ++i) {
        const int off = (i * NT + t) * 16;
        cp16(dst + off, src + off);
    }
    cpcommit();
}

// ---------------------------------------------------------------------------
// prep: split weights into fp16 hi/lo, transpose to [N][K].
// ---------------------------------------------------------------------------
__global__ void prep_kernel(const float* __restrict__ w1,
                            const float* __restrict__ w2,
                            const float* __restrict__ w3)
{
    int g = blockIdx.x * blockDim.x + threadIdx.x;
    if (g >= 270336) return;
    float x; unsigned char* dst; int plane;
    if (g < 262144) {
        int layer = g >> 17;
        int r  = g & 131071;
        int s  = r >> 14;
        int r2 = r & 16383;
        plane  = r2 >> 13;
        int e  = r2 & 8191;
        int n = e >> 5, kl = e & 31;
        const float* w = layer ? w3 : w2;
        x = w[(s * 32 + kl) * 256 + n];
        dst = &g_w23[layer][s][plane * 16384 + n * 64 + kl * 2];
    } else {
        int q = g - 262144;
        plane = q >> 12;
        int e = q & 4095;
        int n = e >> 4, kl = e & 15;
        x = (kl < 13) ? w1[kl * 256 + n] : 0.f;
        dst = &g_w1[plane * 8192 + n * 32 + kl * 2];
    }
    __half h = __float2half_rn(x);
    __half v = plane ? __float2half_rn(x - __half2float(h)) : h;
    *reinterpret_cast<__half*>(dst) = v;
}

// ---------------------------------------------------------------------------
__global__ __launch_bounds__(NT, 1)
void rollout_tc(const float* __restrict__ pos0, const float* __restrict__ wind,
                const float* __restrict__ b1g, const float* __restrict__ b2g,
                const float* __restrict__ b3g,
                const float* __restrict__ wmug, const float* __restrict__ bmug,
                float* __restrict__ out)
{
    extern __shared__ char smem[];
    const unsigned sb = smem_u32(smem);
    const int t = threadIdx.x;
    const unsigned lane = (unsigned)(t & 31);
    const int warp = t >> 5;
    const int wm = warp & 3, wn = warp >> 2;

    float* b1s  = (float*)(smem + SM_B1);
    float* b2s  = (float*)(smem + SM_B2);
    float* b3s  = (float*)(smem + SM_B3);
    float* wmu0 = (float*)(smem + SM_WMU);
    float* wmu1 = (float*)(smem + SM_WMU) + 256;
    float* part = (float*)(smem + SM_PART);
    float* bmus = (float*)(smem + SM_BMU);

    // constants
    for (int i = t; i < 256; i += NT) {
        b1s[i] = b1g[i]; b2s[i] = b2g[i]; b3s[i] = b3g[i];
        wmu0[i] = wmug[2 * i]; wmu1[i] = wmug[2 * i + 1];
    }
    if (t < 2) bmus[t] = bmug[t];

    // resident W1 (group 0), then stage prologue (groups 1,2)
    #pragma unroll
    for (int i = 0; i < 2; ++i) {
        const int off = (i * NT + t) * 16;
        cp16(sb + SM_W1 + off, g_w1 + off);
    }
    cpcommit();
    copy32k(sb + SM_WST,         g_w23[0][0], t);
    copy32k(sb + SM_WST + 32768, g_w23[0][1], t);
    cpwait<2>();            // W1 done; stage groups s0,s1 remain in flight
    __syncthreads();

    // agent state (threads 0..127)
    const int gid = blockIdx.x * AGC + t;
    float px = 0.f, py = 0.f, wx = 0.f, wy = 0.f;
    float mxs = -INFINITY, ss = 0.f, mxr = -INFINITY, sr = 0.f;
    if (t < AGC) {
        px = pos0[gid * 2]; py = pos0[gid * 2 + 1];
        wx = wind[gid * 2]; wy = wind[gid * 2 + 1];
    }

    const unsigned ahib = sb + SM_A, alob = sb + SM_ALO;
    float d[2][8][4];

    #pragma unroll 1
    for (int step = 0; step < NSTEP; ++step) {
        // ---------------- observe -> A cols 0..15 ------------------------
        if (t < AGC) {
            float obs[16];
            obs[0] = px * 0.1f;            obs[1] = py * 0.1f;
            obs[2] = (4.0f  - px) * 0.1f;  obs[3] = (3.0f  - py) * 0.1f;
            obs[4] = (1.75f - px) * 0.1f;  obs[5] = (1.75f - py) * 0.1f;
            obs[6] = (1.75f - px) * 0.1f;  obs[7] = (3.75f - py) * 0.1f;
            obs[8] = (3.75f - px) * 0.1f;  obs[9] = (2.0f  - py) * 0.1f;
            { float dx = px-1.75f, dy = py-1.75f; obs[10] = sqrtf(dx*dx+dy*dy+1e-9f) - 0.38f; }
            { float dx = px-1.75f, dy = py-3.75f; obs[11] = sqrtf(dx*dx+dy*dy+1e-9f) - 0.42f; }
            { float dx = px-3.75f, dy = py-2.0f;  obs[12] = sqrtf(dx*dx+dy*dy+1e-9f) - 0.34f; }
            obs[13] = 0.f; obs[14] = 0.f; obs[15] = 0.f;
            #pragma unroll
            for (int c = 0; c < 8; ++c) {
                const int k = c * 2;
                const int chunk = k >> 3, off = (k & 7) * 2;
                const int p = t * 512 + ((chunk ^ (t & 7)) << 4) + off;
                __half h0 = __float2half_rn(obs[k]);
                __half h1 = __float2half_rn(obs[k + 1]);
                *(__half2*)(smem + SM_A + p) = __halves2half2(h0, h1);
                *(__half2*)(smem + SM_ALO + p) = __halves2half2(
                    __float2half_rn(obs[k]     - __half2float(h0)),
                    __float2half_rn(obs[k + 1] - __half2float(h1)));
            }
        }
        __syncthreads();

        // ---------------- layer 1 (K=16, resident W1) --------------------
        #pragma unroll
        for (int mt = 0; mt < 2; ++mt)
            #pragma unroll
            for (int nt = 0; nt < 8; ++nt)
                #pragma unroll
                for (int q = 0; q < 4; ++q) d[mt][nt][q] = 0.f;
        kstep(d, ahib, alob, 0, sb + SM_W1, sb + SM_W1 + 8192, 0, 32, wm, wn, lane);
        __syncthreads();
        epi<true, false>(d, b1s, smem, wmu0, wmu1, wm, wn, lane);
        __syncthreads();

        // ---------------- layers 2 & 3 (streamed k32 stages) -------------
        #pragma unroll 1
        for (int l = 0; l < 2; ++l) {
            #pragma unroll
            for (int mt = 0; mt < 2; ++mt)
                #pragma unroll
                for (int nt = 0; nt < 8; ++nt)
                    #pragma unroll
                    for (int q = 0; q < 4; ++q) d[mt][nt][q] = 0.f;
            #pragma unroll 1
            for (int s = 0; s < 8; ++s) {
                cpwait<1>();
                __syncthreads();
                const unsigned wb = sb + SM_WST + (unsigned)((s & 1) * 32768);
                kstep(d, ahib, alob, s * 2,     wb, wb + 16384, 0, 64, wm, wn, lane);
                kstep(d, ahib, alob, s * 2 + 1, wb, wb + 16384, 2, 64, wm, wn, lane);
                __syncthreads();
                // flat schedule: copy stage f+2 into the buffer just freed
                const int f = l * 8 + s + 2;      // 2..17
                const int f2 = f & 15;            // wraps to next step's L2
                const unsigned char* src = g_w23[(f2 >> 3) & 1][f2 & 7];
                copy32k(sb + SM_WST + (unsigned)((s & 1) * 32768), src, t);
            }
            if (l == 0) {
                epi<true, false>(d, b2s, smem, wmu0, wmu1, wm, wn, lane);
                __syncthreads();
            } else {
                epi<false, true>(d, b3s, smem, wmu0, wmu1, wm, wn, lane);
                __syncthreads();
            }
        }

        // ---------------- combine output + integrate + margins -----------
        if (t < AGC) {
            float a0 = part[t*4] + part[t*4+1] + part[t*4+2] + part[t*4+3] + bmus[0];
            float a1 = part[512 + t*4] + part[512 + t*4+1]
                     + part[512 + t*4+2] + part[512 + t*4+3] + bmus[1];
            float ax = clampf(a0, -1.f, 1.f), ay = clampf(a1, -1.f, 1.f);
            float vx = 2.f * ax + wx, vy = 2.f * ay + wy;
            #pragma unroll
            for (int s_ = 0; s_ < 4; ++s_) {
                px = clampf(px + 0.0625f * vx, -4.f, 10.f);
                py = clampf(py + 0.0625f * vy, -4.f, 10.f);
            }
            float d0x = px-1.75f, d0y = py-1.75f;
            float c0 = sqrtf(d0x*d0x + d0y*d0y + 1e-9f) - 0.38f;
            float d1x = px-1.75f, d1y = py-3.75f;
            float c1 = sqrtf(d1x*d1x + d1y*d1y + 1e-9f) - 0.42f;
            float d2x = px-3.75f, d2y = py-2.0f;
            float c2 = sqrtf(d2x*d2x + d2y*d2y + 1e-9f) - 0.34f;
            float x0 = -50.f*c0, x1 = -50.f*c1, x2 = -50.f*c2;
            float mM = fmaxf(x0, fmaxf(x1, x2));
            float safe = -(mM + logf(expf(x0-mM) + expf(x1-mM) + expf(x2-mM))) * 0.02f;
            float xs = -8.f * safe;
            if (xs > mxs) { ss = ss * expf(mxs - xs) + 1.f; mxs = xs; }
            else          { ss += expf(xs - mxs); }
            float gx = px - 4.f, gy = py - 3.f;
            float gdist = sqrtf(gx*gx + gy*gy + 1e-9f);
            float xr = 8.f * (0.45f - gdist);
            if (xr > mxr) { sr = sr * expf(mxr - xr) + 1.f; mxr = xr; }
            else          { sr += expf(xr - mxr); }
        }
        __syncthreads();
    }

    cpwait<0>();   // drain trailing prefetches
    if (t < AGC) {
        float rho_safe  = -(mxs + logf(ss)) * 0.125f;
        float rho_reach =  (mxr + logf(sr)) * 0.125f;
        float xa = -8.f * rho_safe, xb = -8.f * rho_reach;
        float mm = fmaxf(xa, xb);
        out[gid] = -(mm + logf(expf(xa - mm) + expf(xb - mm))) * 0.125f;
    }
}

// ---------------------------------------------------------------------------
extern "C" void kernel_launch(void* const* d_in, const int* in_sizes, int n_in,
                              void* d_out, int out_size)
{
    (void)in_sizes; (void)n_in; (void)out_size;
    const float* pos0 = (const float*)d_in[0];
    const float* wind = (const float*)d_in[1];
    const float* w1   = (const float*)d_in[2];
    const float* b1   = (const float*)d_in[3];
    const float* w2   = (const float*)d_in[4];
    const float* b2   = (const float*)d_in[5];
    const float* w3   = (const float*)d_in[6];
    const float* b3   = (const float*)d_in[7];
    const float* wmu  = (const float*)d_in[8];
    const float* bmu  = (const float*)d_in[9];
    float* out = (float*)d_out;

    prep_kernel<<<(270336 + 255) / 256, 256>>>(w1, w2, w3);

    cudaFuncSetAttribute(rollout_tc,
                         cudaFuncAttributeMaxDynamicSharedMemorySize, SM_TOT);
    rollout_tc<<<CTAS, NT, SM_TOT>>>(pos0, wind, b1, b2, b3, wmu, bmu, out);
}

// round 11
// speedup vs baseline: 2.8484x; 1.3368x over previous
#include <cuda_runtime.h>
#include <cuda_fp16.h>
#include <math.h>

// ===========================================================================
// RolloutModule via legacy tensor cores (mma.sync m16n8k16 fp16, fp32 accum).
// Split precision: x = hi + lo (fp16 each); products hi*hi + lo*hi + hi*lo.
// R11: NT=256, 8 warps, warp tile 64x64 (2m x 4n). 256-reg budget lets ptxas
// pipeline LDSM ahead of the 96-MMA-per-kstep chains; 1.5x arithmetic
// intensity vs 32x64 tile. Streaming/sync structure unchanged from R10.
// ===========================================================================

#define NT    256
#define AGC   128
#define CTAS  256
#define NSTEP 64

// smem byte offsets
#define SM_A    0          // A hi plane [128][256] fp16 = 65536
#define SM_ALO  65536      // A lo plane
#define SM_W1   131072     // W1 hi 8192 + lo 8192
#define SM_WST  147456     // 2 stage buffers x 32768 (each: hi[256][32], lo[256][32])
#define SM_B1   212992
#define SM_B2   214016
#define SM_B3   215040
#define SM_WMU  216064     // wmu0[256], wmu1[256] f32
#define SM_PART 218112     // [2][128][4] f32
#define SM_BMU  222208
#define SM_TOT  222336

// Prepared weights (filled by prep kernel every launch)
__device__ __align__(16) unsigned char g_w23[2][8][32768]; // [layer][k32 stage]
__device__ __align__(16) unsigned char g_w1[16384];        // [plane][256][16]

// ---------------------------------------------------------------------------
__device__ __forceinline__ unsigned smem_u32(const void* p) {
    unsigned a;
    asm("{ .reg .u64 t; cvta.to.shared.u64 t, %1; cvt.u32.u64 %0, t; }"
        : "=r"(a) : "l"(p));
    return a;
}
__device__ __forceinline__ void cp16(unsigned d, const void* s) {
    asm volatile("cp.async.cg.shared.global [%0], [%1], 16;" :: "r"(d), "l"(s));
}
__device__ __forceinline__ void cpcommit() { asm volatile("cp.async.commit_group;" ::: "memory"); }
template<int N> __device__ __forceinline__ void cpwait() {
    asm volatile("cp.async.wait_group %0;" :: "n"(N) : "memory");
}

#define LDSM4(r0,r1,r2,r3,a) \
    asm volatile("ldmatrix.sync.aligned.m8n8.x4.shared.b16 {%0,%1,%2,%3}, [%4];" \
        : "=r"(r0),"=r"(r1),"=r"(r2),"=r"(r3) : "r"(a))

#define MMA(dd, a, b0, b1) \
    asm volatile("mma.sync.aligned.m16n8k16.row.col.f32.f16.f16.f32 " \
        "{%0,%1,%2,%3},{%4,%5,%6,%7},{%8,%9},{%0,%1,%2,%3};" \
        : "+f"((dd)[0]),"+f"((dd)[1]),"+f"((dd)[2]),"+f"((dd)[3]) \
        : "r"((a)[0]),"r"((a)[1]),"r"((a)[2]),"r"((a)[3]),"r"(b0),"r"(b1))

__device__ __forceinline__ float clampf(float v, float lo, float hi) {
    return fminf(fmaxf(v, lo), hi);
}

// A fragment (m16 x k16) from swizzled [128][256] fp16 plane.
__device__ __forceinline__ void ldA(unsigned abase, int mbase, int k16,
                                    unsigned lane, unsigned* r) {
    int row = mbase + (int)(((lane >> 3) & 1) << 3) + (int)(lane & 7);
    int kc  = k16 * 2 + (int)(lane >> 4);
    unsigned addr = abase + (unsigned)(row * 512) +
                    ((unsigned)(kc ^ (row & 7)) << 4);
    LDSM4(r[0], r[1], r[2], r[3], addr);
}

// B n16 x k16 fragment from [N][K] fp16, row stride rs bytes.
// r[0],r[1] = n8 #0 (klo,khi); r[2],r[3] = n8 #1.
__device__ __forceinline__ void ldB(unsigned wbase, int nbase, int kc0, int rs,
                                    unsigned lane, unsigned* r) {
    int nrow = nbase + (int)((lane >> 4) << 3) + (int)(lane & 7);
    int kc   = kc0 + (int)((lane >> 3) & 1);
    unsigned addr = wbase + (unsigned)(nrow * rs) + ((unsigned)kc << 4);
    LDSM4(r[0], r[1], r[2], r[3], addr);
}

// One k16 step over warp tile 64x64: 3-product split MMA, 96 MMAs.
__device__ __forceinline__ void kstep(float (*d)[8][4],
                                      unsigned ahib, unsigned alob, int k16,
                                      unsigned whib, unsigned wlob,
                                      int kc0loc, int rs,
                                      int wm, int wn, unsigned lane)
{
    unsigned ah[4][4], al[4][4];
    #pragma unroll
    for (int mt = 0; mt < 4; ++mt) {
        ldA(ahib, wm * 64 + mt * 16, k16, lane, ah[mt]);
        ldA(alob, wm * 64 + mt * 16, k16, lane, al[mt]);
    }
    #pragma unroll
    for (int g = 0; g < 4; ++g) {
        unsigned bh4[4], bl4[4];
        ldB(whib, wn * 64 + g * 16, kc0loc, rs, lane, bh4);
        ldB(wlob, wn * 64 + g * 16, kc0loc, rs, lane, bl4);
        #pragma unroll
        for (int mt = 0; mt < 4; ++mt)
            #pragma unroll
            for (int q = 0; q < 2; ++q) {
                const int nt = g * 2 + q;
                MMA(d[mt][nt], ah[mt], bh4[q * 2], bh4[q * 2 + 1]);
                MMA(d[mt][nt], al[mt], bh4[q * 2], bh4[q * 2 + 1]);
                MMA(d[mt][nt], ah[mt], bl4[q * 2], bl4[q * 2 + 1]);
            }
    }
}

// Epilogue: bias+relu; STORE -> write hi/lo planes; DOT -> output-layer dots.
template<bool STORE, bool DOT>
__device__ __forceinline__ void epi(float (*d)[8][4], const float* bias,
                                    char* smem, const float* wmu0,
                                    const float* wmu1,
                                    int wm, int wn, unsigned lane)
{
    const int qrow = (int)(lane >> 2);
    const int qn   = (int)(lane & 3) * 2;
    float* part = (float*)(smem + SM_PART);
    #pragma unroll
    for (int mt = 0; mt < 4; ++mt) {
        const int r0 = wm * 64 + mt * 16 + qrow;
        const int r1 = r0 + 8;
        float s0a = 0.f, s1a = 0.f, s0b = 0.f, s1b = 0.f;
        #pragma unroll
        for (int nt = 0; nt < 8; ++nt) {
            const int n = wn * 64 + nt * 8 + qn;
            const float bb0 = bias[n], bb1 = bias[n + 1];
            float v0 = fmaxf(d[mt][nt][0] + bb0, 0.f);
            float v1 = fmaxf(d[mt][nt][1] + bb1, 0.f);
            float v2 = fmaxf(d[mt][nt][2] + bb0, 0.f);
            float v3 = fmaxf(d[mt][nt][3] + bb1, 0.f);
            if (DOT) {
                s0a = fmaf(v0, wmu0[n], fmaf(v1, wmu0[n + 1], s0a));
                s1a = fmaf(v0, wmu1[n], fmaf(v1, wmu1[n + 1], s1a));
                s0b = fmaf(v2, wmu0[n], fmaf(v3, wmu0[n + 1], s0b));
                s1b = fmaf(v2, wmu1[n], fmaf(v3, wmu1[n + 1], s1b));
            }
            if (STORE) {
                const int chunk = n >> 3, off = (n & 7) * 2;
                __half h0 = __float2half_rn(v0), h1 = __float2half_rn(v1);
                __half h2 = __float2half_rn(v2), h3 = __float2half_rn(v3);
                __half2 hp0 = __halves2half2(h0, h1);
                __half2 hp1 = __halves2half2(h2, h3);
                __half2 lp0 = __halves2half2(
                    __float2half_rn(v0 - __half2float(h0)),
                    __float2half_rn(v1 - __half2float(h1)));
                __half2 lp1 = __halves2half2(
                    __float2half_rn(v2 - __half2float(h2)),
                    __float2half_rn(v3 - __half2float(h3)));
                const int p0 = r0 * 512 + ((chunk ^ (r0 & 7)) << 4) + off;
                const int p1 = r1 * 512 + ((chunk ^ (r1 & 7)) << 4) + off;
                *(__half2*)(smem + SM_A   + p0) = hp0;
                *(__half2*)(smem + SM_ALO + p0) = lp0;
                *(__half2*)(smem + SM_A   + p1) = hp1;
                *(__half2*)(smem + SM_ALO + p1) = lp1;
            }
        }
        if (DOT) {
            s0a += __shfl_xor_sync(0xffffffffu, s0a, 1);
            s0a += __shfl_xor_sync(0xffffffffu, s0a, 2);
            s1a += __shfl_xor_sync(0xffffffffu, s1a, 1);
            s1a += __shfl_xor_sync(0xffffffffu, s1a, 2);
            s0b += __shfl_xor_sync(0xffffffffu, s0b, 1);
            s0b += __shfl_xor_sync(0xffffffffu, s0b, 2);
            s1b += __shfl_xor_sync(0xffffffffu, s1b, 1);
            s1b += __shfl_xor_sync(0xffffffffu, s1b, 2);
            if ((lane & 3) == 0) {
                part[r0 * 4 + wn]       = s0a;
                part[512 + r0 * 4 + wn] = s1a;
                part[r1 * 4 + wn]       = s0b;
                part[512 + r1 * 4 + wn] = s1b;
            }
        }
    }
}

__device__ __forceinline__ void copy32k(unsigned dst, const unsigned char* src, int t) {
    #pragma unroll
    for (int i = 0; i < 8; ++i) {
        const int off = (i * NT + t) * 16;
        cp16(dst + off, src + off);
    }
    cpcommit();
}

// ---------------------------------------------------------------------------
// prep: split weights into fp16 hi/lo, transpose to [N][K].
// ---------------------------------------------------------------------------
__global__ void prep_kernel(const float* __restrict__ w1,
                            const float* __restrict__ w2,
                            const float* __restrict__ w3)
{
    int g = blockIdx.x * blockDim.x + threadIdx.x;
    if (g >= 270336) return;
    float x; unsigned char* dst; int plane;
    if (g < 262144) {
        int layer = g >> 17;
        int r  = g & 131071;
        int s  = r >> 14;
        int r2 = r & 16383;
        plane  = r2 >> 13;
        int e  = r2 & 8191;
        int n = e >> 5, kl = e & 31;
        const float* w = layer ? w3 : w2;
        x = w[(s * 32 + kl) * 256 + n];
        dst = &g_w23[layer][s][plane * 16384 + n * 64 + kl * 2];
    } else {
        int q = g - 262144;
        plane = q >> 12;
        int e = q & 4095;
        int n = e >> 4, kl = e & 15;
        x = (kl < 13) ? w1[kl * 256 + n] : 0.f;
        dst = &g_w1[plane * 8192 + n * 32 + kl * 2];
    }
    __half h = __float2half_rn(x);
    __half v = plane ? __float2half_rn(x - __half2float(h)) : h;
    *reinterpret_cast<__half*>(dst) = v;
}

// ---------------------------------------------------------------------------
__global__ __launch_bounds__(NT, 1)
void rollout_tc(const float* __restrict__ pos0, const float* __restrict__ wind,
                const float* __restrict__ b1g, const float* __restrict__ b2g,
                const float* __restrict__ b3g,
                const float* __restrict__ wmug, const float* __restrict__ bmug,
                float* __restrict__ out)
{
    extern __shared__ char smem[];
    const unsigned sb = smem_u32(smem);
    const int t = threadIdx.x;
    const unsigned lane = (unsigned)(t & 31);
    const int warp = t >> 5;
    const int wm = warp & 1, wn = warp >> 1;   // 2m x 4n, warp tile 64x64

    float* b1s  = (float*)(smem + SM_B1);
    float* b2s  = (float*)(smem + SM_B2);
    float* b3s  = (float*)(smem + SM_B3);
    float* wmu0 = (float*)(smem + SM_WMU);
    float* wmu1 = (float*)(smem + SM_WMU) + 256;
    float* part = (float*)(smem + SM_PART);
    float* bmus = (float*)(smem + SM_BMU);

    // constants
    for (int i = t; i < 256; i += NT) {
        b1s[i] = b1g[i]; b2s[i] = b2g[i]; b3s[i] = b3g[i];
        wmu0[i] = wmug[2 * i]; wmu1[i] = wmug[2 * i + 1];
    }
    if (t < 2) bmus[t] = bmug[t];

    // resident W1 (group 0), then stage prologue (groups 1,2)
    #pragma unroll
    for (int i = 0; i < 4; ++i) {
        const int off = (i * NT + t) * 16;
        cp16(sb + SM_W1 + off, g_w1 + off);
    }
    cpcommit();
    copy32k(sb + SM_WST,         g_w23[0][0], t);
    copy32k(sb + SM_WST + 32768, g_w23[0][1], t);
    cpwait<2>();            // W1 done; stage groups s0,s1 remain in flight
    __syncthreads();

    // agent state (threads 0..127)
    const int gid = blockIdx.x * AGC + t;
    float px = 0.f, py = 0.f, wx = 0.f, wy = 0.f;
    float mxs = -INFINITY, ss = 0.f, mxr = -INFINITY, sr = 0.f;
    if (t < AGC) {
        px = pos0[gid * 2]; py = pos0[gid * 2 + 1];
        wx = wind[gid * 2]; wy = wind[gid * 2 + 1];
    }

    const unsigned ahib = sb + SM_A, alob = sb + SM_ALO;
    float d[4][8][4];

    #pragma unroll 1
    for (int step = 0; step < NSTEP; ++step) {
        // ---------------- observe -> A cols 0..15 ------------------------
        if (t < AGC) {
            float obs[16];
            obs[0] = px * 0.1f;            obs[1] = py * 0.1f;
            obs[2] = (4.0f  - px) * 0.1f;  obs[3] = (3.0f  - py) * 0.1f;
            obs[4] = (1.75f - px) * 0.1f;  obs[5] = (1.75f - py) * 0.1f;
            obs[6] = (1.75f - px) * 0.1f;  obs[7] = (3.75f - py) * 0.1f;
            obs[8] = (3.75f - px) * 0.1f;  obs[9] = (2.0f  - py) * 0.1f;
            { float dx = px-1.75f, dy = py-1.75f; obs[10] = sqrtf(dx*dx+dy*dy+1e-9f) - 0.38f; }
            { float dx = px-1.75f, dy = py-3.75f; obs[11] = sqrtf(dx*dx+dy*dy+1e-9f) - 0.42f; }
            { float dx = px-3.75f, dy = py-2.0f;  obs[12] = sqrtf(dx*dx+dy*dy+1e-9f) - 0.34f; }
            obs[13] = 0.f; obs[14] = 0.f; obs[15] = 0.f;
            #pragma unroll
            for (int c = 0; c < 8; ++c) {
                const int k = c * 2;
                const int chunk = k >> 3, off = (k & 7) * 2;
                const int p = t * 512 + ((chunk ^ (t & 7)) << 4) + off;
                __half h0 = __float2half_rn(obs[k]);
                __half h1 = __float2half_rn(obs[k + 1]);
                *(__half2*)(smem + SM_A + p) = __halves2half2(h0, h1);
                *(__half2*)(smem + SM_ALO + p) = __halves2half2(
                    __float2half_rn(obs[k]     - __half2float(h0)),
                    __float2half_rn(obs[k + 1] - __half2float(h1)));
            }
        }
        __syncthreads();

        // ---------------- layer 1 (K=16, resident W1) --------------------
        #pragma unroll
        for (int mt = 0; mt < 4; ++mt)
            #pragma unroll
            for (int nt = 0; nt < 8; ++nt)
                #pragma unroll
                for (int q = 0; q < 4; ++q) d[mt][nt][q] = 0.f;
        kstep(d, ahib, alob, 0, sb + SM_W1, sb + SM_W1 + 8192, 0, 32, wm, wn, lane);
        __syncthreads();
        epi<true, false>(d, b1s, smem, wmu0, wmu1, wm, wn, lane);
        __syncthreads();

        // ---------------- layers 2 & 3 (streamed k32 stages) -------------
        #pragma unroll 1
        for (int l = 0; l < 2; ++l) {
            #pragma unroll
            for (int mt = 0; mt < 4; ++mt)
                #pragma unroll
                for (int nt = 0; nt < 8; ++nt)
                    #pragma unroll
                    for (int q = 0; q < 4; ++q) d[mt][nt][q] = 0.f;
            #pragma unroll 1
            for (int s = 0; s < 8; ++s) {
                cpwait<1>();
                __syncthreads();
                const unsigned wb = sb + SM_WST + (unsigned)((s & 1) * 32768);
                kstep(d, ahib, alob, s * 2,     wb, wb + 16384, 0, 64, wm, wn, lane);
                kstep(d, ahib, alob, s * 2 + 1, wb, wb + 16384, 2, 64, wm, wn, lane);
                __syncthreads();
                // flat schedule: copy stage f+2 into the buffer just freed
                const int f = l * 8 + s + 2;      // 2..17
                const int f2 = f & 15;            // wraps to next step's L2
                const unsigned char* src = g_w23[(f2 >> 3) & 1][f2 & 7];
                copy32k(sb + SM_WST + (unsigned)((s & 1) * 32768), src, t);
            }
            if (l == 0) {
                epi<true, false>(d, b2s, smem, wmu0, wmu1, wm, wn, lane);
                __syncthreads();
            } else {
                epi<false, true>(d, b3s, smem, wmu0, wmu1, wm, wn, lane);
                __syncthreads();
            }
        }

        // ---------------- combine output + integrate + margins -----------
        if (t < AGC) {
            float a0 = part[t*4] + part[t*4+1] + part[t*4+2] + part[t*4+3] + bmus[0];
            float a1 = part[512 + t*4] + part[512 + t*4+1]
                     + part[512 + t*4+2] + part[512 + t*4+3] + bmus[1];
            float ax = clampf(a0, -1.f, 1.f), ay = clampf(a1, -1.f, 1.f);
            float vx = 2.f * ax + wx, vy = 2.f * ay + wy;
            #pragma unroll
            for (int s_ = 0; s_ < 4; ++s_) {
                px = clampf(px + 0.0625f * vx, -4.f, 10.f);
                py = clampf(py + 0.0625f * vy, -4.f, 10.f);
            }
            float d0x = px-1.75f, d0y = py-1.75f;
            float c0 = sqrtf(d0x*d0x + d0y*d0y + 1e-9f) - 0.38f;
            float d1x = px-1.75f, d1y = py-3.75f;
            float c1 = sqrtf(d1x*d1x + d1y*d1y + 1e-9f) - 0.42f;
            float d2x = px-3.75f, d2y = py-2.0f;
            float c2 = sqrtf(d2x*d2x + d2y*d2y + 1e-9f) - 0.34f;
            float x0 = -50.f*c0, x1 = -50.f*c1, x2 = -50.f*c2;
            float mM = fmaxf(x0, fmaxf(x1, x2));
            float safe = -(mM + logf(expf(x0-mM) + expf(x1-mM) + expf(x2-mM))) * 0.02f;
            float xs = -8.f * safe;
            if (xs > mxs) { ss = ss * expf(mxs - xs) + 1.f; mxs = xs; }
            else          { ss += expf(xs - mxs); }
            float gx = px - 4.f, gy = py - 3.f;
            float gdist = sqrtf(gx*gx + gy*gy + 1e-9f);
            float xr = 8.f * (0.45f - gdist);
            if (xr > mxr) { sr = sr * expf(mxr - xr) + 1.f; mxr = xr; }
            else          { sr += expf(xr - mxr); }
        }
        __syncthreads();
    }

    cpwait<0>();   // drain trailing prefetches
    if (t < AGC) {
        float rho_safe  = -(mxs + logf(ss)) * 0.125f;
        float rho_reach =  (mxr + logf(sr)) * 0.125f;
        float xa = -8.f * rho_safe, xb = -8.f * rho_reach;
        float mm = fmaxf(xa, xb);
        out[gid] = -(mm + logf(expf(xa - mm) + expf(xb - mm))) * 0.125f;
    }
}

// ---------------------------------------------------------------------------
extern "C" void kernel_launch(void* const* d_in, const int* in_sizes, int n_in,
                              void* d_out, int out_size)
{
    (void)in_sizes; (void)n_in; (void)out_size;
    const float* pos0 = (const float*)d_in[0];
    const float* wind = (const float*)d_in[1];
    const float* w1   = (const float*)d_in[2];
    const float* b1   = (const float*)d_in[3];
    const float* w2   = (const float*)d_in[4];
    const float* b2   = (const float*)d_in[5];
    const float* w3   = (const float*)d_in[6];
    const float* b3   = (const float*)d_in[7];
    const float* wmu  = (const float*)d_in[8];
    const float* bmu  = (const float*)d_in[9];
    float* out = (float*)d_out;

    prep_kernel<<<(270336 + 255) / 256, 256>>>(w1, w2, w3);

    cudaFuncSetAttribute(rollout_tc,
                         cudaFuncAttributeMaxDynamicSharedMemorySize, SM_TOT);
    rollout_tc<<<CTAS, NT, SM_TOT>>>(pos0, wind, b1, b2, b3, wmu, bmu, out);
}

// round 12
// speedup vs baseline: 2.9849x; 1.0479x over previous
#include <cuda_runtime.h>
#include <cuda_fp16.h>
#include <math.h>

// ===========================================================================
// RolloutModule via legacy tensor cores (mma.sync m16n8k16 fp16, fp32 accum).
// Split precision: hi*hi + lo*hi + hi*lo.  NT=256, 8 warps, warp tile 64x64.
// R12: pair-local weight pipeline — warp pair wn stages/consumes only its own
// 8KB B-slice per k32 stage, synced with 64-thread named barriers instead of
// CTA-wide __syncthreads (32 -> 0 CTA bars in the stage loops; 8 remain per
// step at A-plane boundaries). Bias folded into accumulator init.
// ===========================================================================

#define NT    256
#define AGC   128
#define CTAS  256
#define NSTEP 64

// smem byte offsets
#define SM_A    0          // A hi plane [128][256] fp16 = 65536
#define SM_ALO  65536      // A lo plane
#define SM_W1   131072     // W1 hi 8192 + lo 8192
#define SM_WST  147456     // 2 stage buffers x 32768 (each: hi[256][32], lo[256][32])
#define SM_B1   212992
#define SM_B2   214016
#define SM_B3   215040
#define SM_WMU  216064     // wmu0[256], wmu1[256] f32
#define SM_PART 218112     // [2][128][4] f32
#define SM_BMU  222208
#define SM_TOT  222336

__device__ __align__(16) unsigned char g_w23[2][8][32768]; // [layer][k32 stage]
__device__ __align__(16) unsigned char g_w1[16384];        // [plane][256][16]

// ---------------------------------------------------------------------------
__device__ __forceinline__ unsigned smem_u32(const void* p) {
    unsigned a;
    asm("{ .reg .u64 t; cvta.to.shared.u64 t, %1; cvt.u32.u64 %0, t; }"
        : "=r"(a) : "l"(p));
    return a;
}
__device__ __forceinline__ void cp16(unsigned d, const void* s) {
    asm volatile("cp.async.cg.shared.global [%0], [%1], 16;" :: "r"(d), "l"(s));
}
__device__ __forceinline__ void cpcommit() { asm volatile("cp.async.commit_group;" ::: "memory"); }
template<int N> __device__ __forceinline__ void cpwait() {
    asm volatile("cp.async.wait_group %0;" :: "n"(N) : "memory");
}
__device__ __forceinline__ void barpair(int wn) {
    asm volatile("bar.sync %0, 64;" :: "r"(wn + 1) : "memory");
}

#define LDSM4(r0,r1,r2,r3,a) \
    asm volatile("ldmatrix.sync.aligned.m8n8.x4.shared.b16 {%0,%1,%2,%3}, [%4];" \
        : "=r"(r0),"=r"(r1),"=r"(r2),"=r"(r3) : "r"(a))

#define MMA(dd, a, b0, b1) \
    asm volatile("mma.sync.aligned.m16n8k16.row.col.f32.f16.f16.f32 " \
        "{%0,%1,%2,%3},{%4,%5,%6,%7},{%8,%9},{%0,%1,%2,%3};" \
        : "+f"((dd)[0]),"+f"((dd)[1]),"+f"((dd)[2]),"+f"((dd)[3]) \
        : "r"((a)[0]),"r"((a)[1]),"r"((a)[2]),"r"((a)[3]),"r"(b0),"r"(b1))

__device__ __forceinline__ float clampf(float v, float lo, float hi) {
    return fminf(fmaxf(v, lo), hi);
}

// A fragment (m16 x k16) from swizzled [128][256] fp16 plane.
__device__ __forceinline__ void ldA(unsigned abase, int mbase, int k16,
                                    unsigned lane, unsigned* r) {
    int row = mbase + (int)(((lane >> 3) & 1) << 3) + (int)(lane & 7);
    int kc  = k16 * 2 + (int)(lane >> 4);
    unsigned addr = abase + (unsigned)(row * 512) +
                    ((unsigned)(kc ^ (row & 7)) << 4);
    LDSM4(r[0], r[1], r[2], r[3], addr);
}

// B n16 x k16 fragment from [N][K] fp16, row stride rs bytes.
__device__ __forceinline__ void ldB(unsigned wbase, int nbase, int kc0, int rs,
                                    unsigned lane, unsigned* r) {
    int nrow = nbase + (int)((lane >> 4) << 3) + (int)(lane & 7);
    int kc   = kc0 + (int)((lane >> 3) & 1);
    unsigned addr = wbase + (unsigned)(nrow * rs) + ((unsigned)kc << 4);
    LDSM4(r[0], r[1], r[2], r[3], addr);
}

// One k16 step over warp tile 64x64: 3-product split MMA, 96 MMAs.
__device__ __forceinline__ void kstep(float (*d)[8][4],
                                      unsigned ahib, unsigned alob, int k16,
                                      unsigned whib, unsigned wlob,
                                      int kc0loc, int rs,
                                      int wm, int wn, unsigned lane)
{
    unsigned ah[4][4], al[4][4];
    #pragma unroll
    for (int mt = 0; mt < 4; ++mt) {
        ldA(ahib, wm * 64 + mt * 16, k16, lane, ah[mt]);
        ldA(alob, wm * 64 + mt * 16, k16, lane, al[mt]);
    }
    #pragma unroll
    for (int g = 0; g < 4; ++g) {
        unsigned bh4[4], bl4[4];
        ldB(whib, wn * 64 + g * 16, kc0loc, rs, lane, bh4);
        ldB(wlob, wn * 64 + g * 16, kc0loc, rs, lane, bl4);
        #pragma unroll
        for (int mt = 0; mt < 4; ++mt)
            #pragma unroll
            for (int q = 0; q < 2; ++q) {
                const int nt = g * 2 + q;
                MMA(d[mt][nt], ah[mt], bh4[q * 2], bh4[q * 2 + 1]);
                MMA(d[mt][nt], al[mt], bh4[q * 2], bh4[q * 2 + 1]);
                MMA(d[mt][nt], ah[mt], bl4[q * 2], bl4[q * 2 + 1]);
            }
    }
}

// Init accumulators with bias (bias already added -> epilogue skips it).
__device__ __forceinline__ void init_acc(float (*d)[8][4], const float* bias,
                                         int wn, int qn)
{
    float bb[8][2];
    #pragma unroll
    for (int nt = 0; nt < 8; ++nt) {
        const int n = wn * 64 + nt * 8 + qn;
        bb[nt][0] = bias[n]; bb[nt][1] = bias[n + 1];
    }
    #pragma unroll
    for (int mt = 0; mt < 4; ++mt)
        #pragma unroll
        for (int nt = 0; nt < 8; ++nt) {
            d[mt][nt][0] = bb[nt][0]; d[mt][nt][1] = bb[nt][1];
            d[mt][nt][2] = bb[nt][0]; d[mt][nt][3] = bb[nt][1];
        }
}

// Epilogue: relu (bias pre-added); STORE -> write hi/lo planes; DOT -> dots.
template<bool STORE, bool DOT>
__device__ __forceinline__ void epi(float (*d)[8][4],
                                    char* smem, const float* wmu0,
                                    const float* wmu1,
                                    int wm, int wn, unsigned lane)
{
    const int qrow = (int)(lane >> 2);
    const int qn   = (int)(lane & 3) * 2;
    float* part = (float*)(smem + SM_PART);
    #pragma unroll
    for (int mt = 0; mt < 4; ++mt) {
        const int r0 = wm * 64 + mt * 16 + qrow;
        const int r1 = r0 + 8;
        float s0a = 0.f, s1a = 0.f, s0b = 0.f, s1b = 0.f;
        #pragma unroll
        for (int nt = 0; nt < 8; ++nt) {
            const int n = wn * 64 + nt * 8 + qn;
            float v0 = fmaxf(d[mt][nt][0], 0.f);
            float v1 = fmaxf(d[mt][nt][1], 0.f);
            float v2 = fmaxf(d[mt][nt][2], 0.f);
            float v3 = fmaxf(d[mt][nt][3], 0.f);
            if (DOT) {
                s0a = fmaf(v0, wmu0[n], fmaf(v1, wmu0[n + 1], s0a));
                s1a = fmaf(v0, wmu1[n], fmaf(v1, wmu1[n + 1], s1a));
                s0b = fmaf(v2, wmu0[n], fmaf(v3, wmu0[n + 1], s0b));
                s1b = fmaf(v2, wmu1[n], fmaf(v3, wmu1[n + 1], s1b));
            }
            if (STORE) {
                const int chunk = n >> 3, off = (n & 7) * 2;
                __half2 hp0 = __float22half2_rn(make_float2(v0, v1));
                __half2 hp1 = __float22half2_rn(make_float2(v2, v3));
                __half2 lp0 = __float22half2_rn(make_float2(
                    v0 - __low2float(hp0), v1 - __high2float(hp0)));
                __half2 lp1 = __float22half2_rn(make_float2(
                    v2 - __low2float(hp1), v3 - __high2float(hp1)));
                const int p0 = r0 * 512 + ((chunk ^ (r0 & 7)) << 4) + off;
                const int p1 = r1 * 512 + ((chunk ^ (r1 & 7)) << 4) + off;
                *(__half2*)(smem + SM_A   + p0) = hp0;
                *(__half2*)(smem + SM_ALO + p0) = lp0;
                *(__half2*)(smem + SM_A   + p1) = hp1;
                *(__half2*)(smem + SM_ALO + p1) = lp1;
            }
        }
        if (DOT) {
            s0a += __shfl_xor_sync(0xffffffffu, s0a, 1);
            s0a += __shfl_xor_sync(0xffffffffu, s0a, 2);
            s1a += __shfl_xor_sync(0xffffffffu, s1a, 1);
            s1a += __shfl_xor_sync(0xffffffffu, s1a, 2);
            s0b += __shfl_xor_sync(0xffffffffu, s0b, 1);
            s0b += __shfl_xor_sync(0xffffffffu, s0b, 2);
            s1b += __shfl_xor_sync(0xffffffffu, s1b, 1);
            s1b += __shfl_xor_sync(0xffffffffu, s1b, 2);
            if ((lane & 3) == 0) {
                part[r0 * 4 + wn]       = s0a;
                part[512 + r0 * 4 + wn] = s1a;
                part[r1 * 4 + wn]       = s0b;
                part[512 + r1 * 4 + wn] = s1b;
            }
        }
    }
}

// Per-warp slice copy: warp wm copies plane wm, rows [wn*64, wn*64+64) (4KB).
__device__ __forceinline__ void copy_slice(unsigned dstbuf,
                                           const unsigned char* srcstage,
                                           int wm, int wn, unsigned lane)
{
    const unsigned base = (unsigned)(wm * 16384 + wn * 4096);
    #pragma unroll
    for (int i = 0; i < 8; ++i) {
        const unsigned off = base + (unsigned)((i * 32 + (int)lane) * 16);
        cp16(dstbuf + off, srcstage + off);
    }
    cpcommit();
}

// ---------------------------------------------------------------------------
// prep: split weights into fp16 hi/lo, transpose to [N][K].
// ---------------------------------------------------------------------------
__global__ void prep_kernel(const float* __restrict__ w1,
                            const float* __restrict__ w2,
                            const float* __restrict__ w3)
{
    int g = blockIdx.x * blockDim.x + threadIdx.x;
    if (g >= 270336) return;
    float x; unsigned char* dst; int plane;
    if (g < 262144) {
        int layer = g >> 17;
        int r  = g & 131071;
        int s  = r >> 14;
        int r2 = r & 16383;
        plane  = r2 >> 13;
        int e  = r2 & 8191;
        int n = e >> 5, kl = e & 31;
        const float* w = layer ? w3 : w2;
        x = w[(s * 32 + kl) * 256 + n];
        dst = &g_w23[layer][s][plane * 16384 + n * 64 + kl * 2];
    } else {
        int q = g - 262144;
        plane = q >> 12;
        int e = q & 4095;
        int n = e >> 4, kl = e & 15;
        x = (kl < 13) ? w1[kl * 256 + n] : 0.f;
        dst = &g_w1[plane * 8192 + n * 32 + kl * 2];
    }
    __half h = __float2half_rn(x);
    __half v = plane ? __float2half_rn(x - __half2float(h)) : h;
    *reinterpret_cast<__half*>(dst) = v;
}

// ---------------------------------------------------------------------------
__global__ __launch_bounds__(NT, 1)
void rollout_tc(const float* __restrict__ pos0, const float* __restrict__ wind,
                const float* __restrict__ b1g, const float* __restrict__ b2g,
                const float* __restrict__ b3g,
                const float* __restrict__ wmug, const float* __restrict__ bmug,
                float* __restrict__ out)
{
    extern __shared__ char smem[];
    const unsigned sb = smem_u32(smem);
    const int t = threadIdx.x;
    const unsigned lane = (unsigned)(t & 31);
    const int warp = t >> 5;
    const int wm = warp & 1, wn = warp >> 1;   // 2m x 4n, warp tile 64x64
    const int qn = (int)(lane & 3) * 2;

    float* b1s  = (float*)(smem + SM_B1);
    float* b2s  = (float*)(smem + SM_B2);
    float* b3s  = (float*)(smem + SM_B3);
    float* wmu0 = (float*)(smem + SM_WMU);
    float* wmu1 = (float*)(smem + SM_WMU) + 256;
    float* part = (float*)(smem + SM_PART);
    float* bmus = (float*)(smem + SM_BMU);

    // constants
    for (int i = t; i < 256; i += NT) {
        b1s[i] = b1g[i]; b2s[i] = b2g[i]; b3s[i] = b3g[i];
        wmu0[i] = wmug[2 * i]; wmu1[i] = wmug[2 * i + 1];
    }
    if (t < 2) bmus[t] = bmug[t];

    // resident W1 (group 0, CTA-wide), then per-warp slice prologue (s0, s1)
    #pragma unroll
    for (int i = 0; i < 4; ++i) {
        const int off = (i * NT + t) * 16;
        cp16(sb + SM_W1 + off, g_w1 + off);
    }
    cpcommit();
    copy_slice(sb + SM_WST,         g_w23[0][0], wm, wn, lane);
    copy_slice(sb + SM_WST + 32768, g_w23[0][1], wm, wn, lane);
    cpwait<2>();            // W1 done; slice groups s0,s1 remain in flight
    __syncthreads();

    // agent state (threads 0..127)
    const int gid = blockIdx.x * AGC + t;
    float px = 0.f, py = 0.f, wx = 0.f, wy = 0.f;
    float mxs = -INFINITY, ss = 0.f, mxr = -INFINITY, sr = 0.f;
    if (t < AGC) {
        px = pos0[gid * 2]; py = pos0[gid * 2 + 1];
        wx = wind[gid * 2]; wy = wind[gid * 2 + 1];
    }

    const unsigned ahib = sb + SM_A, alob = sb + SM_ALO;
    float d[4][8][4];

    #pragma unroll 1
    for (int step = 0; step < NSTEP; ++step) {
        // ---------------- observe -> A cols 0..15 ------------------------
        if (t < AGC) {
            float obs[16];
            obs[0] = px * 0.1f;            obs[1] = py * 0.1f;
            obs[2] = (4.0f  - px) * 0.1f;  obs[3] = (3.0f  - py) * 0.1f;
            obs[4] = (1.75f - px) * 0.1f;  obs[5] = (1.75f - py) * 0.1f;
            obs[6] = (1.75f - px) * 0.1f;  obs[7] = (3.75f - py) * 0.1f;
            obs[8] = (3.75f - px) * 0.1f;  obs[9] = (2.0f  - py) * 0.1f;
            { float dx = px-1.75f, dy = py-1.75f; obs[10] = sqrtf(dx*dx+dy*dy+1e-9f) - 0.38f; }
            { float dx = px-1.75f, dy = py-3.75f; obs[11] = sqrtf(dx*dx+dy*dy+1e-9f) - 0.42f; }
            { float dx = px-3.75f, dy = py-2.0f;  obs[12] = sqrtf(dx*dx+dy*dy+1e-9f) - 0.34f; }
            obs[13] = 0.f; obs[14] = 0.f; obs[15] = 0.f;
            #pragma unroll
            for (int c = 0; c < 8; ++c) {
                const int k = c * 2;
                const int chunk = k >> 3, off = (k & 7) * 2;
                const int p = t * 512 + ((chunk ^ (t & 7)) << 4) + off;
                __half2 hp = __float22half2_rn(make_float2(obs[k], obs[k + 1]));
                *(__half2*)(smem + SM_A + p) = hp;
                *(__half2*)(smem + SM_ALO + p) = __float22half2_rn(make_float2(
                    obs[k]     - __low2float(hp),
                    obs[k + 1] - __high2float(hp)));
            }
        }
        __syncthreads();

        // ---------------- layer 1 (K=16, resident W1) --------------------
        init_acc(d, b1s, wn, qn);
        kstep(d, ahib, alob, 0, sb + SM_W1, sb + SM_W1 + 8192, 0, 32, wm, wn, lane);
        __syncthreads();
        epi<true, false>(d, smem, wmu0, wmu1, wm, wn, lane);
        __syncthreads();

        // ---------------- layers 2 & 3 (streamed k32 stages) -------------
        #pragma unroll 1
        for (int l = 0; l < 2; ++l) {
            init_acc(d, l ? b3s : b2s, wn, qn);
            #pragma unroll 1
            for (int s = 0; s < 8; ++s) {
                cpwait<1>();          // own slice of stage s landed
                barpair(wn);          // partner's slice landed too
                const unsigned wb = sb + SM_WST + (unsigned)((s & 1) * 32768);
                kstep(d, ahib, alob, s * 2,     wb, wb + 16384, 0, 64, wm, wn, lane);
                kstep(d, ahib, alob, s * 2 + 1, wb, wb + 16384, 2, 64, wm, wn, lane);
                barpair(wn);          // pair finished reading this buffer
                // flat schedule: copy stage f+2 into the buffer just freed
                const int f2 = (l * 8 + s + 2) & 15;   // wraps to next step's L2
                copy_slice(sb + SM_WST + (unsigned)((s & 1) * 32768),
                           g_w23[(f2 >> 3) & 1][f2 & 7], wm, wn, lane);
            }
            __syncthreads();          // all warps done reading A for this layer
            if (l == 0) {
                epi<true, false>(d, smem, wmu0, wmu1, wm, wn, lane);
                __syncthreads();      // A(l+1) fully written
            } else {
                epi<false, true>(d, smem, wmu0, wmu1, wm, wn, lane);
                __syncthreads();      // part[] written
            }
        }

        // ---------------- combine output + integrate + margins -----------
        if (t < AGC) {
            float a0 = part[t*4] + part[t*4+1] + part[t*4+2] + part[t*4+3] + bmus[0];
            float a1 = part[512 + t*4] + part[512 + t*4+1]
                     + part[512 + t*4+2] + part[512 + t*4+3] + bmus[1];
            float ax = clampf(a0, -1.f, 1.f), ay = clampf(a1, -1.f, 1.f);
            float vx = 2.f * ax + wx, vy = 2.f * ay + wy;
            #pragma unroll
            for (int s_ = 0; s_ < 4; ++s_) {
                px = clampf(px + 0.0625f * vx, -4.f, 10.f);
                py = clampf(py + 0.0625f * vy, -4.f, 10.f);
            }
            float d0x = px-1.75f, d0y = py-1.75f;
            float c0 = sqrtf(d0x*d0x + d0y*d0y + 1e-9f) - 0.38f;
            float d1x = px-1.75f, d1y = py-3.75f;
            float c1 = sqrtf(d1x*d1x + d1y*d1y + 1e-9f) - 0.42f;
            float d2x = px-3.75f, d2y = py-2.0f;
            float c2 = sqrtf(d2x*d2x + d2y*d2y + 1e-9f) - 0.34f;
            float x0 = -50.f*c0, x1 = -50.f*c1, x2 = -50.f*c2;
            float mM = fmaxf(x0, fmaxf(x1, x2));
            float safe = -(mM + logf(expf(x0-mM) + expf(x1-mM) + expf(x2-mM))) * 0.02f;
            float xs = -8.f * safe;
            if (xs > mxs) { ss = ss * expf(mxs - xs) + 1.f; mxs = xs; }
            else          { ss += expf(xs - mxs); }
            float gx = px - 4.f, gy = py - 3.f;
            float gdist = sqrtf(gx*gx + gy*gy + 1e-9f);
            float xr = 8.f * (0.45f - gdist);
            if (xr > mxr) { sr = sr * expf(mxr - xr) + 1.f; mxr = xr; }
            else          { sr += expf(xr - mxr); }
        }
        __syncthreads();
    }

    cpwait<0>();   // drain trailing prefetches
    if (t < AGC) {
        float rho_safe  = -(mxs + logf(ss)) * 0.125f;
        float rho_reach =  (mxr + logf(sr)) * 0.125f;
        float xa = -8.f * rho_safe, xb = -8.f * rho_reach;
        float mm = fmaxf(xa, xb);
        out[gid] = -(mm + logf(expf(xa - mm) + expf(xb - mm))) * 0.125f;
    }
}

// ---------------------------------------------------------------------------
extern "C" void kernel_launch(void* const* d_in, const int* in_sizes, int n_in,
                              void* d_out, int out_size)
{
    (void)in_sizes; (void)n_in; (void)out_size;
    const float* pos0 = (const float*)d_in[0];
    const float* wind = (const float*)d_in[1];
    const float* w1   = (const float*)d_in[2];
    const float* b1   = (const float*)d_in[3];
    const float* w2   = (const float*)d_in[4];
    const float* b2   = (const float*)d_in[5];
    const float* w3   = (const float*)d_in[6];
    const float* b3   = (const float*)d_in[7];
    const float* wmu  = (const float*)d_in[8];
    const float* bmu  = (const float*)d_in[9];
    float* out = (float*)d_out;

    prep_kernel<<<(270336 + 255) / 256, 256>>>(w1, w2, w3);

    cudaFuncSetAttribute(rollout_tc,
                         cudaFuncAttributeMaxDynamicSharedMemorySize, SM_TOT);
    rollout_tc<<<CTAS, NT, SM_TOT>>>(pos0, wind, b1, b2, b3, wmu, bmu, out);
}